// round 11
// baseline (speedup 1.0000x reference)
#include <cuda_runtime.h>

#define S_   4
#define B_   8
#define L_   512
#define D_   128
#define NOP_ 64
#define W_   2048   // S_*L_

// ---------------- scratch (device globals; no allocation) ----------------
__device__ float g_agg[B_ * W_ * 3 * D_];   // per selected word: [h_o | a_k(normed) | a_s(normed)]
__device__ float g_coef[B_ * W_ * 4];       // [-, rowsumK, rowsumS]
__device__ float g_opproj[B_ * NOP_ * D_];  // op_embedding @ o_w_W + o_w_b
__device__ float g_goal[B_ * D_];           // pooled sum of relu(word_updated)
__device__ float g_p1[B_ * D_];             // split-K partials for k_final
__device__ float g_p2[B_ * D_];
__device__ int   g_fcnt[B_];
__device__ int   g_bcnt[B_];
__device__ int   g_list[B_ * W_];
__device__ int   g_n;

// ---------------- helpers ----------------
__device__ __forceinline__ void add4(float4& a, const float4 v) {
    a.x += v.x; a.y += v.y; a.z += v.z; a.w += v.w;
}
__device__ __forceinline__ void team_bar(int tg) {
    asm volatile("bar.sync %0, 64;" :: "r"(tg + 1) : "memory");
}
// packed f32x2 fma: d.lo += a.lo*b.lo; d.hi += a.hi*b.hi
__device__ __forceinline__ void ffma2(unsigned long long& d, unsigned long long a, unsigned long long b) {
    asm("fma.rn.f32x2 %0, %1, %2, %0;" : "+l"(d) : "l"(a), "l"(b));
}
__device__ __forceinline__ unsigned long long pack2(float x, float y) {
    unsigned long long r;
    asm("mov.b64 %0, {%1, %2};" : "=l"(r) : "f"(x), "f"(y));
    return r;
}
__device__ __forceinline__ float2 unpack2(unsigned long long v) {
    float2 r;
    asm("mov.b64 {%0, %1}, %2;" : "=f"(r.x), "=f"(r.y) : "l"(v));
    return r;
}

// ---------------- kernel 1: op projection (+ reset) ----------------
__global__ void __launch_bounds__(1024) k_opproj(
    const float* __restrict__ op_embedding,
    const float* __restrict__ o_w_W, const float* __restrict__ o_w_b)
{
    const int og = blockIdx.x, b = blockIdx.y;
    const int tid = threadIdx.x;
    const int ol = tid >> 7, h = tid & 127;

    if (og == 0 && b == 0) {           // fold all resets into this kernel
        if (tid < B_ * D_) { g_goal[tid] = 0.f; g_p1[tid] = 0.f; g_p2[tid] = 0.f; }
        if (tid < B_) { g_bcnt[tid] = 0; g_fcnt[tid] = 0; }
        if (tid == 0) g_n = 0;
    }

    __shared__ float es[8][128];
    const int o = og * 8 + ol;
    es[ol][h] = op_embedding[((size_t)(b * NOP_ + o)) * D_ + h];
    __syncthreads();

    float acc = o_w_b[h];
    #pragma unroll 8
    for (int dd = 0; dd < 128; ++dd)
        acc = fmaf(es[ol][dd], o_w_W[dd * 128 + h], acc);
    g_opproj[((size_t)(b * NOP_ + o)) * D_ + h] = acc;
}

// ---------------- kernel 2: aggregate neighbors ----------------
__global__ void __launch_bounds__(128) k_aggregate(
    const float* __restrict__ word_outputs,
    const float* __restrict__ word_operator,
    const float* __restrict__ word_word,
    const float* __restrict__ depend_relation,
    const float* __restrict__ word_exist_matrix,
    const float* __restrict__ word_exist_seq,
    const float* __restrict__ goal_word)
{
    const int w = blockIdx.x, b = blockIdx.y;
    const int bw = b * W_ + w;
    if (goal_word[bw] == 0.f || word_exist_seq[bw] == 0.f) return;

    const int tid = threadIdx.x;
    const int lane = tid & 31, wid = tid >> 5;
    const unsigned lt = (1u << lane) - 1u;

    __shared__ int   listK[4][512];
    __shared__ int   listS[4][128];
    __shared__ int   listO[64];
    __shared__ float comb[4][3][128];
    __shared__ int   scn[4][2];

    float4 accO = {0,0,0,0}, accK = {0,0,0,0}, accS = {0,0,0,0};
    int cK = 0, cS = 0;

    // ---- operator part: gather pre-projected rows (H-space), warp 0 only ----
    if (wid == 0) {
        const float4* wo4 = (const float4*)(word_operator + (size_t)bw * NOP_);
        float4 m = (lane < 16) ? wo4[lane] : make_float4(0.f,0.f,0.f,0.f);
        int col0 = lane * 4, cO = 0;
        unsigned bb;
        bb = __ballot_sync(0xffffffffu, m.x != 0.f); if (m.x != 0.f) listO[cO + __popc(bb & lt)] = col0;     cO += __popc(bb);
        bb = __ballot_sync(0xffffffffu, m.y != 0.f); if (m.y != 0.f) listO[cO + __popc(bb & lt)] = col0 + 1; cO += __popc(bb);
        bb = __ballot_sync(0xffffffffu, m.z != 0.f); if (m.z != 0.f) listO[cO + __popc(bb & lt)] = col0 + 2; cO += __popc(bb);
        bb = __ballot_sync(0xffffffffu, m.w != 0.f); if (m.w != 0.f) listO[cO + __popc(bb & lt)] = col0 + 3; cO += __popc(bb);
        __syncwarp();
        const float* pb = g_opproj + (size_t)b * NOP_ * D_;
        float4 o0 = {0,0,0,0}, o1 = {0,0,0,0};
        int i = 0;
        for (; i + 2 <= cO; i += 2) {
            float4 v0 = ((const float4*)(pb + (size_t)listO[i]     * D_))[lane];
            float4 v1 = ((const float4*)(pb + (size_t)listO[i + 1] * D_))[lane];
            add4(o0, v0); add4(o1, v1);
        }
        if (i < cO) add4(o0, ((const float4*)(pb + (size_t)listO[i] * D_))[lane]);
        accO = o0; add4(accO, o1);
    }

    // ---- knowledge part: word_word * word_exist_matrix over 2048 cols ----
    {
        const float4* ww4 = (const float4*)(word_word + (size_t)bw * W_);
        const float4* we4 = (const float4*)(word_exist_matrix + (size_t)bw * W_);
        const int cbase = wid * 512;
        #pragma unroll
        for (int c4 = 0; c4 < 4; ++c4) {
            int vec = wid * 128 + c4 * 32 + lane;
            float4 m1 = ww4[vec], m2 = we4[vec];
            float mx = m1.x * m2.x, my = m1.y * m2.y, mz = m1.z * m2.z, mw = m1.w * m2.w;
            int col0 = cbase + c4 * 128 + lane * 4;
            unsigned bb;
            bb = __ballot_sync(0xffffffffu, mx != 0.f); if (mx != 0.f) listK[wid][cK + __popc(bb & lt)] = col0;     cK += __popc(bb);
            bb = __ballot_sync(0xffffffffu, my != 0.f); if (my != 0.f) listK[wid][cK + __popc(bb & lt)] = col0 + 1; cK += __popc(bb);
            bb = __ballot_sync(0xffffffffu, mz != 0.f); if (mz != 0.f) listK[wid][cK + __popc(bb & lt)] = col0 + 2; cK += __popc(bb);
            bb = __ballot_sync(0xffffffffu, mw != 0.f); if (mw != 0.f) listK[wid][cK + __popc(bb & lt)] = col0 + 3; cK += __popc(bb);
        }
        __syncwarp();
        float4 acc8[8];
        #pragma unroll
        for (int q = 0; q < 8; ++q) acc8[q] = make_float4(0.f,0.f,0.f,0.f);
        int i = 0;
        for (; i + 8 <= cK; i += 8) {
            #pragma unroll
            for (int q = 0; q < 8; ++q) {
                int j = listK[wid][i + q];
                float4 v = ((const float4*)(word_outputs + (((size_t)(j >> 9) * B_ + b) * L_ + (j & 511)) * D_))[lane];
                add4(acc8[q], v);
            }
        }
        for (; i < cK; ++i) {
            int j = listK[wid][i];
            add4(acc8[0], ((const float4*)(word_outputs + (((size_t)(j >> 9) * B_ + b) * L_ + (j & 511)) * D_))[lane]);
        }
        add4(acc8[0], acc8[1]); add4(acc8[2], acc8[3]); add4(acc8[4], acc8[5]); add4(acc8[6], acc8[7]);
        add4(acc8[0], acc8[2]); add4(acc8[4], acc8[6]);
        accK = acc8[0]; add4(accK, acc8[4]);
    }

    // ---- segment dependency part: 512 cols, same segment ----
    {
        const int s = w >> 9, l = w & 511;
        const float4* dp4 = (const float4*)(depend_relation + (((size_t)s * B_ + b) * L_ + l) * L_);
        const float* xb = word_outputs + ((size_t)s * B_ + b) * L_ * D_;
        float4 m = dp4[wid * 32 + lane];
        int col0 = wid * 128 + lane * 4;
        unsigned bb;
        bb = __ballot_sync(0xffffffffu, m.x != 0.f); if (m.x != 0.f) listS[wid][cS + __popc(bb & lt)] = col0;     cS += __popc(bb);
        bb = __ballot_sync(0xffffffffu, m.y != 0.f); if (m.y != 0.f) listS[wid][cS + __popc(bb & lt)] = col0 + 1; cS += __popc(bb);
        bb = __ballot_sync(0xffffffffu, m.z != 0.f); if (m.z != 0.f) listS[wid][cS + __popc(bb & lt)] = col0 + 2; cS += __popc(bb);
        bb = __ballot_sync(0xffffffffu, m.w != 0.f); if (m.w != 0.f) listS[wid][cS + __popc(bb & lt)] = col0 + 3; cS += __popc(bb);
        __syncwarp();
        float4 acc8[8];
        #pragma unroll
        for (int q = 0; q < 8; ++q) acc8[q] = make_float4(0.f,0.f,0.f,0.f);
        int i = 0;
        for (; i + 8 <= cS; i += 8) {
            #pragma unroll
            for (int q = 0; q < 8; ++q)
                add4(acc8[q], ((const float4*)(xb + (size_t)listS[wid][i + q] * D_))[lane]);
        }
        for (; i < cS; ++i)
            add4(acc8[0], ((const float4*)(xb + (size_t)listS[wid][i] * D_))[lane]);
        add4(acc8[0], acc8[1]); add4(acc8[2], acc8[3]); add4(acc8[4], acc8[5]); add4(acc8[6], acc8[7]);
        add4(acc8[0], acc8[2]); add4(acc8[4], acc8[6]);
        accS = acc8[0]; add4(accS, acc8[4]);
    }

    // ---- cross-warp combine ----
    *(float4*)&comb[wid][0][4 * lane] = accO;
    *(float4*)&comb[wid][1][4 * lane] = accK;
    *(float4*)&comb[wid][2][4 * lane] = accS;
    if (lane == 0) { scn[wid][0] = cK; scn[wid][1] = cS; }
    __syncthreads();

    const int d = tid;
    float aO = comb[0][0][d] + comb[1][0][d] + comb[2][0][d] + comb[3][0][d];
    float aK = comb[0][1][d] + comb[1][1][d] + comb[2][1][d] + comb[3][1][d];
    float aS = comb[0][2][d] + comb[1][2][d] + comb[2][2][d] + comb[3][2][d];
    int tK = scn[0][0] + scn[1][0] + scn[2][0] + scn[3][0];
    int tS = scn[0][1] + scn[1][1] + scn[2][1] + scn[3][1];
    float invK = 1.f / ((float)tK + 1e-30f);
    float invS = 1.f / ((float)tS + 1e-30f);

    float* ag = g_agg + (size_t)bw * 384;
    ag[d]       = aO;               // H-space, bias included
    ag[128 + d] = aK * invK;
    ag[256 + d] = aS * invS;
    if (tid == 0) {
        g_coef[bw * 4 + 1] = (float)tK * invK;
        g_coef[bw * 4 + 2] = (float)tS * invS;
        int pos = atomicAdd(&g_n, 1);
        g_list[pos] = bw;
        atomicAdd(&g_bcnt[b], 1);
    }
}

// ---------------- kernel 3: GEMVs + norm + up-proj (packed f32x2) ----------------
// 2-warp teams, 8 words each, lane owns 2 output dims packed in one f32x2.
// Aggregates staged in smem PRE-DUPLICATED ({a,a} pairs): source dim dd lives
// at float offset dd*2, so K-chunk s4 (source dims 4*s4..4*s4+3) starts at
// float offset s4*8. One LDS.128 yields two packed broadcast operands.
__global__ void __launch_bounds__(256) k_update(
    const float* __restrict__ wk_W, const float* __restrict__ wk_b,
    const float* __restrict__ ws_W, const float* __restrict__ ws_b,
    const float* __restrict__ up_W, const float* __restrict__ up_b)
{
    const int tid = threadIdx.x;
    const int lane = tid & 31, wid = tid >> 5;
    const int half = wid & 1, tg = wid >> 1;
    const int t64 = tid & 63;
    const int team = blockIdx.x * 4 + tg;
    const int nteams = gridDim.x * 4;
    const int N = g_n;
    const int dim0 = half * 64 + lane * 2;

    __shared__ __align__(16) float as2[4][8][256];   // duplicated pairs, 32 KB
    __shared__ float ssp[4][8][2];

    typedef unsigned long long ull;
    const float2 bUf = *(const float2*)(up_b + dim0);

    for (int base = team * 8; base < N; base += nteams * 8) {
        int idx[8]; bool val[8];
        #pragma unroll
        for (int g = 0; g < 8; ++g) {
            val[g] = (base + g) < N;
            idx[g] = val[g] ? g_list[base + g] : 0;
        }
        ull u[8];
        #pragma unroll
        for (int g = 0; g < 8; ++g) u[g] = pack2(bUf.x, bUf.y);

        #pragma unroll
        for (int p = 0; p < 3; ++p) {
            // stage duplicated aggregates: 8 words x 64 pairs
            #pragma unroll
            for (int r = 0; r < 8; ++r) {
                int q = r * 64 + t64;
                int g = q >> 6, pr = q & 63;
                float2 v = val[g] ? *(const float2*)(g_agg + (size_t)idx[g] * 384 + p * 128 + pr * 2)
                                  : make_float2(0.f, 0.f);
                *(float4*)(&as2[tg][g][pr * 4]) = make_float4(v.x, v.x, v.y, v.y);
            }
            team_bar(tg);

            ull h[8];
            if (p == 0) {
                #pragma unroll
                for (int g = 0; g < 8; ++g) {
                    float4 t = *(const float4*)(&as2[tg][g][dim0 * 2]);
                    h[g] = pack2(t.x, t.z);
                }
            } else {
                const float* Wp = (p == 1) ? wk_W : ws_W;
                const float* bp = (p == 1) ? wk_b : ws_b;
                const float2 bia = *(const float2*)(bp + dim0);
                #pragma unroll
                for (int g = 0; g < 8; ++g) {
                    float cf = val[g] ? g_coef[idx[g] * 4 + p] : 0.f;
                    h[g] = pack2(cf * bia.x, cf * bia.y);
                }
                #pragma unroll 4
                for (int s4 = 0; s4 < 32; ++s4) {
                    ull w0 = *(const ull*)(Wp + (s4 * 4 + 0) * 128 + dim0);
                    ull w1 = *(const ull*)(Wp + (s4 * 4 + 1) * 128 + dim0);
                    ull w2 = *(const ull*)(Wp + (s4 * 4 + 2) * 128 + dim0);
                    ull w3 = *(const ull*)(Wp + (s4 * 4 + 3) * 128 + dim0);
                    #pragma unroll
                    for (int g = 0; g < 8; ++g) {
                        ulonglong2 a01 = *(const ulonglong2*)(&as2[tg][g][s4 * 8]);
                        ulonglong2 a23 = *(const ulonglong2*)(&as2[tg][g][s4 * 8 + 4]);
                        ffma2(h[g], a01.x, w0); ffma2(h[g], a01.y, w1);
                        ffma2(h[g], a23.x, w2); ffma2(h[g], a23.y, w3);
                    }
                }
            }
            // L2 norm across team
            float2 hf[8];
            #pragma unroll
            for (int g = 0; g < 8; ++g) {
                hf[g] = unpack2(h[g]);
                float ss = hf[g].x * hf[g].x + hf[g].y * hf[g].y;
                ss += __shfl_xor_sync(0xffffffffu, ss, 16);
                ss += __shfl_xor_sync(0xffffffffu, ss, 8);
                ss += __shfl_xor_sync(0xffffffffu, ss, 4);
                ss += __shfl_xor_sync(0xffffffffu, ss, 2);
                ss += __shfl_xor_sync(0xffffffffu, ss, 1);
                if (lane == 0) ssp[tg][g][half] = ss;
            }
            team_bar(tg);   // also orders all GEMV smem reads before writeback
            #pragma unroll
            for (int g = 0; g < 8; ++g) {
                float inv = 1.f / (sqrtf(ssp[tg][g][0] + ssp[tg][g][1]) + 1e-30f);
                float nx = hf[g].x * inv, ny = hf[g].y * inv;
                *(float4*)(&as2[tg][g][dim0 * 2]) = make_float4(nx, nx, ny, ny);
            }
            team_bar(tg);
            // up-projection for this part
            const float* Up = up_W + (size_t)p * 128 * 128;
            #pragma unroll 4
            for (int s4 = 0; s4 < 32; ++s4) {
                ull w0 = *(const ull*)(Up + (s4 * 4 + 0) * 128 + dim0);
                ull w1 = *(const ull*)(Up + (s4 * 4 + 1) * 128 + dim0);
                ull w2 = *(const ull*)(Up + (s4 * 4 + 2) * 128 + dim0);
                ull w3 = *(const ull*)(Up + (s4 * 4 + 3) * 128 + dim0);
                #pragma unroll
                for (int g = 0; g < 8; ++g) {
                    ulonglong2 a01 = *(const ulonglong2*)(&as2[tg][g][s4 * 8]);
                    ulonglong2 a23 = *(const ulonglong2*)(&as2[tg][g][s4 * 8 + 4]);
                    ffma2(u[g], a01.x, w0); ffma2(u[g], a01.y, w1);
                    ffma2(u[g], a23.x, w2); ffma2(u[g], a23.y, w3);
                }
            }
            team_bar(tg);   // protect as2 reuse by next part
        }
        // relu + pooled accumulation
        #pragma unroll
        for (int g = 0; g < 8; ++g) {
            if (val[g]) {
                int b = idx[g] >> 11;
                float2 uf = unpack2(u[g]);
                atomicAdd(g_goal + b * 128 + dim0,     fmaxf(uf.x, 0.f));
                atomicAdd(g_goal + b * 128 + dim0 + 1, fmaxf(uf.y, 0.f));
            }
        }
    }
}

// ---------------- kernel 4: gates + output, split-K over 64 blocks ----------------
__global__ void __launch_bounds__(128) k_final(
    const float* __restrict__ node_hidden,
    const float* __restrict__ wg_W, const float* __restrict__ wg_b,
    const float* __restrict__ fg_W, const float* __restrict__ fg_b,
    float* __restrict__ out)
{
    const int b = blockIdx.x >> 3, kq = blockIdx.x & 7;
    const int d = threadIdx.x;
    __shared__ float xk[48];
    __shared__ int lastflag;

    float inv = 1.f / ((float)g_bcnt[b] + 1e-30f);
    if (d < 16) xk[d] = g_goal[b * 128 + kq * 16 + d] * inv;
    else if (d < 48) {
        int k2 = kq * 32 + (d - 16);
        xk[d] = (k2 < 128) ? g_goal[b * 128 + k2] * inv : node_hidden[b * 128 + k2 - 128];
    }
    __syncthreads();

    float s1 = 0.f, s2 = 0.f;
    #pragma unroll
    for (int i = 0; i < 16; ++i)
        s1 = fmaf(xk[i], wg_W[(kq * 16 + i) * 128 + d], s1);
    #pragma unroll
    for (int i = 0; i < 32; ++i)
        s2 = fmaf(xk[16 + i], fg_W[(kq * 32 + i) * 128 + d], s2);

    atomicAdd(&g_p1[b * 128 + d], s1);
    atomicAdd(&g_p2[b * 128 + d], s2);
    __threadfence();
    __syncthreads();
    if (d == 0) lastflag = (atomicAdd(&g_fcnt[b], 1) == 7) ? 1 : 0;
    __syncthreads();

    if (lastflag) {
        float t1 = __ldcg(&g_p1[b * 128 + d]) + wg_b[d];
        float t2 = __ldcg(&g_p2[b * 128 + d]) + fg_b[d];
        float nh = node_hidden[b * 128 + d];
        float gu = fmaxf(t1, 0.f);
        float f  = 1.f / (1.f + expf(-t2));
        out[b * 128 + d] = fmaxf(f, 0.1f) * nh + (1.f - f) * gu;
    }
}

// ---------------- launch ----------------
extern "C" void kernel_launch(void* const* d_in, const int* in_sizes, int n_in,
                              void* d_out, int out_size) {
    const float* word_outputs      = (const float*)d_in[0];
    const float* node_hidden       = (const float*)d_in[1];
    const float* op_embedding      = (const float*)d_in[2];
    const float* word_operator     = (const float*)d_in[3];
    const float* word_word         = (const float*)d_in[4];
    const float* depend_relation   = (const float*)d_in[5];
    const float* word_exist_matrix = (const float*)d_in[6];
    const float* word_exist_seq    = (const float*)d_in[7];
    const float* goal_word         = (const float*)d_in[8];
    const float* o_w_W = (const float*)d_in[9];
    const float* o_w_b = (const float*)d_in[10];
    const float* wk_W  = (const float*)d_in[11];
    const float* wk_b  = (const float*)d_in[12];
    const float* ws_W  = (const float*)d_in[13];
    const float* ws_b  = (const float*)d_in[14];
    const float* up_W  = (const float*)d_in[15];
    const float* up_b  = (const float*)d_in[16];
    const float* wg_W  = (const float*)d_in[17];
    const float* wg_b  = (const float*)d_in[18];
    const float* fg_W  = (const float*)d_in[19];
    const float* fg_b  = (const float*)d_in[20];
    float* out = (float*)d_out;

    k_opproj<<<dim3(8, 8), 1024>>>(op_embedding, o_w_W, o_w_b);
    k_aggregate<<<dim3(W_, B_), 128>>>(word_outputs, word_operator, word_word,
                                       depend_relation, word_exist_matrix,
                                       word_exist_seq, goal_word);
    k_update<<<148, 256>>>(wk_W, wk_b, ws_W, ws_b, up_W, up_b);
    k_final<<<64, 128>>>(node_hidden, wg_W, wg_b, fg_W, fg_b, out);
}

// round 12
// speedup vs baseline: 1.0298x; 1.0298x over previous
#include <cuda_runtime.h>

#define S_   4
#define B_   8
#define L_   512
#define D_   128
#define NOP_ 64
#define W_   2048   // S_*L_
#define NBLK_ 148
#define NTEAMS_ 592          // NBLK_ * 4
#define GMAIN_ 5             // words per team, main pass (592*5 = 2960 ~= N)

// ---------------- scratch (device globals; no allocation) ----------------
__device__ float g_agg[B_ * W_ * 3 * D_];   // per selected word: [h_o | a_k(normed) | a_s(normed)]
__device__ float g_coef[B_ * W_ * 4];       // [-, rowsumK, rowsumS]
__device__ float g_opproj[B_ * NOP_ * D_];  // op_embedding @ o_w_W + o_w_b
__device__ float g_goal[B_ * D_];           // pooled sum of relu(word_updated)
__device__ int   g_bcnt[B_];
__device__ int   g_list[B_ * W_];
__device__ int   g_n;
__device__ int   g_done;

// ---------------- helpers ----------------
__device__ __forceinline__ void add4(float4& a, const float4 v) {
    a.x += v.x; a.y += v.y; a.z += v.z; a.w += v.w;
}
__device__ __forceinline__ void team_bar(int tg) {
    asm volatile("bar.sync %0, 64;" :: "r"(tg + 1) : "memory");
}

// ---------------- kernel 1: op projection (+ reset) ----------------
__global__ void __launch_bounds__(1024) k_opproj(
    const float* __restrict__ op_embedding,
    const float* __restrict__ o_w_W, const float* __restrict__ o_w_b)
{
    const int og = blockIdx.x, b = blockIdx.y;
    const int tid = threadIdx.x;
    const int ol = tid >> 7, h = tid & 127;

    if (og == 0 && b == 0) {           // fold all resets into this kernel
        if (tid < B_ * D_) g_goal[tid] = 0.f;
        if (tid < B_) g_bcnt[tid] = 0;
        if (tid == 0) { g_n = 0; g_done = 0; }
    }

    __shared__ float es[8][128];
    const int o = og * 8 + ol;
    es[ol][h] = op_embedding[((size_t)(b * NOP_ + o)) * D_ + h];
    __syncthreads();

    float acc = o_w_b[h];
    #pragma unroll 8
    for (int dd = 0; dd < 128; ++dd)
        acc = fmaf(es[ol][dd], o_w_W[dd * 128 + h], acc);
    g_opproj[((size_t)(b * NOP_ + o)) * D_ + h] = acc;
}

// ---------------- kernel 2: aggregate neighbors (proven R3 form) ----------------
__global__ void __launch_bounds__(128) k_aggregate(
    const float* __restrict__ word_outputs,
    const float* __restrict__ word_operator,
    const float* __restrict__ word_word,
    const float* __restrict__ depend_relation,
    const float* __restrict__ word_exist_matrix,
    const float* __restrict__ word_exist_seq,
    const float* __restrict__ goal_word)
{
    const int w = blockIdx.x, b = blockIdx.y;
    const int bw = b * W_ + w;
    if (goal_word[bw] == 0.f || word_exist_seq[bw] == 0.f) return;

    const int tid = threadIdx.x;
    const int lane = tid & 31, wid = tid >> 5;
    const unsigned lt = (1u << lane) - 1u;

    __shared__ int   listK[4][512];
    __shared__ int   listS[4][128];
    __shared__ int   listO[64];
    __shared__ float comb[4][3][128];
    __shared__ int   scn[4][2];

    float4 accO = {0,0,0,0}, accK = {0,0,0,0}, accS = {0,0,0,0};
    int cK = 0, cS = 0;

    // ---- operator part: gather pre-projected rows (H-space), warp 0 only ----
    if (wid == 0) {
        const float4* wo4 = (const float4*)(word_operator + (size_t)bw * NOP_);
        float4 m = (lane < 16) ? wo4[lane] : make_float4(0.f,0.f,0.f,0.f);
        int col0 = lane * 4, cO = 0;
        unsigned bb;
        bb = __ballot_sync(0xffffffffu, m.x != 0.f); if (m.x != 0.f) listO[cO + __popc(bb & lt)] = col0;     cO += __popc(bb);
        bb = __ballot_sync(0xffffffffu, m.y != 0.f); if (m.y != 0.f) listO[cO + __popc(bb & lt)] = col0 + 1; cO += __popc(bb);
        bb = __ballot_sync(0xffffffffu, m.z != 0.f); if (m.z != 0.f) listO[cO + __popc(bb & lt)] = col0 + 2; cO += __popc(bb);
        bb = __ballot_sync(0xffffffffu, m.w != 0.f); if (m.w != 0.f) listO[cO + __popc(bb & lt)] = col0 + 3; cO += __popc(bb);
        __syncwarp();
        const float* pb = g_opproj + (size_t)b * NOP_ * D_;
        float4 o0 = {0,0,0,0}, o1 = {0,0,0,0};
        int i = 0;
        for (; i + 2 <= cO; i += 2) {
            float4 v0 = ((const float4*)(pb + (size_t)listO[i]     * D_))[lane];
            float4 v1 = ((const float4*)(pb + (size_t)listO[i + 1] * D_))[lane];
            add4(o0, v0); add4(o1, v1);
        }
        if (i < cO) add4(o0, ((const float4*)(pb + (size_t)listO[i] * D_))[lane]);
        accO = o0; add4(accO, o1);
    }

    // ---- knowledge part: word_word * word_exist_matrix over 2048 cols ----
    {
        const float4* ww4 = (const float4*)(word_word + (size_t)bw * W_);
        const float4* we4 = (const float4*)(word_exist_matrix + (size_t)bw * W_);
        const int cbase = wid * 512;
        #pragma unroll
        for (int c4 = 0; c4 < 4; ++c4) {
            int vec = wid * 128 + c4 * 32 + lane;
            float4 m1 = ww4[vec], m2 = we4[vec];
            float mx = m1.x * m2.x, my = m1.y * m2.y, mz = m1.z * m2.z, mw = m1.w * m2.w;
            int col0 = cbase + c4 * 128 + lane * 4;
            unsigned bb;
            bb = __ballot_sync(0xffffffffu, mx != 0.f); if (mx != 0.f) listK[wid][cK + __popc(bb & lt)] = col0;     cK += __popc(bb);
            bb = __ballot_sync(0xffffffffu, my != 0.f); if (my != 0.f) listK[wid][cK + __popc(bb & lt)] = col0 + 1; cK += __popc(bb);
            bb = __ballot_sync(0xffffffffu, mz != 0.f); if (mz != 0.f) listK[wid][cK + __popc(bb & lt)] = col0 + 2; cK += __popc(bb);
            bb = __ballot_sync(0xffffffffu, mw != 0.f); if (mw != 0.f) listK[wid][cK + __popc(bb & lt)] = col0 + 3; cK += __popc(bb);
        }
        __syncwarp();
        float4 k0 = {0,0,0,0}, k1 = {0,0,0,0}, k2 = {0,0,0,0}, k3 = {0,0,0,0};
        int i = 0;
        for (; i + 4 <= cK; i += 4) {
            int j0 = listK[wid][i], j1 = listK[wid][i+1], j2 = listK[wid][i+2], j3 = listK[wid][i+3];
            float4 v0 = ((const float4*)(word_outputs + (((size_t)(j0 >> 9) * B_ + b) * L_ + (j0 & 511)) * D_))[lane];
            float4 v1 = ((const float4*)(word_outputs + (((size_t)(j1 >> 9) * B_ + b) * L_ + (j1 & 511)) * D_))[lane];
            float4 v2 = ((const float4*)(word_outputs + (((size_t)(j2 >> 9) * B_ + b) * L_ + (j2 & 511)) * D_))[lane];
            float4 v3 = ((const float4*)(word_outputs + (((size_t)(j3 >> 9) * B_ + b) * L_ + (j3 & 511)) * D_))[lane];
            add4(k0, v0); add4(k1, v1); add4(k2, v2); add4(k3, v3);
        }
        for (; i < cK; ++i) {
            int j0 = listK[wid][i];
            add4(k0, ((const float4*)(word_outputs + (((size_t)(j0 >> 9) * B_ + b) * L_ + (j0 & 511)) * D_))[lane]);
        }
        add4(k0, k1); add4(k2, k3); accK = k0; add4(accK, k2);
    }

    // ---- segment dependency part: 512 cols, same segment ----
    {
        const int s = w >> 9, l = w & 511;
        const float4* dp4 = (const float4*)(depend_relation + (((size_t)s * B_ + b) * L_ + l) * L_);
        const float* xb = word_outputs + ((size_t)s * B_ + b) * L_ * D_;
        float4 m = dp4[wid * 32 + lane];
        int col0 = wid * 128 + lane * 4;
        unsigned bb;
        bb = __ballot_sync(0xffffffffu, m.x != 0.f); if (m.x != 0.f) listS[wid][cS + __popc(bb & lt)] = col0;     cS += __popc(bb);
        bb = __ballot_sync(0xffffffffu, m.y != 0.f); if (m.y != 0.f) listS[wid][cS + __popc(bb & lt)] = col0 + 1; cS += __popc(bb);
        bb = __ballot_sync(0xffffffffu, m.z != 0.f); if (m.z != 0.f) listS[wid][cS + __popc(bb & lt)] = col0 + 2; cS += __popc(bb);
        bb = __ballot_sync(0xffffffffu, m.w != 0.f); if (m.w != 0.f) listS[wid][cS + __popc(bb & lt)] = col0 + 3; cS += __popc(bb);
        __syncwarp();
        float4 s0 = {0,0,0,0}, s1 = {0,0,0,0}, s2 = {0,0,0,0}, s3 = {0,0,0,0};
        int i = 0;
        for (; i + 4 <= cS; i += 4) {
            int j0 = listS[wid][i], j1 = listS[wid][i+1], j2 = listS[wid][i+2], j3 = listS[wid][i+3];
            float4 v0 = ((const float4*)(xb + (size_t)j0 * D_))[lane];
            float4 v1 = ((const float4*)(xb + (size_t)j1 * D_))[lane];
            float4 v2 = ((const float4*)(xb + (size_t)j2 * D_))[lane];
            float4 v3 = ((const float4*)(xb + (size_t)j3 * D_))[lane];
            add4(s0, v0); add4(s1, v1); add4(s2, v2); add4(s3, v3);
        }
        for (; i < cS; ++i)
            add4(s0, ((const float4*)(xb + (size_t)listS[wid][i] * D_))[lane]);
        add4(s0, s1); add4(s2, s3); accS = s0; add4(accS, s2);
    }

    // ---- cross-warp combine ----
    *(float4*)&comb[wid][0][4 * lane] = accO;
    *(float4*)&comb[wid][1][4 * lane] = accK;
    *(float4*)&comb[wid][2][4 * lane] = accS;
    if (lane == 0) { scn[wid][0] = cK; scn[wid][1] = cS; }
    __syncthreads();

    const int d = tid;
    float aO = comb[0][0][d] + comb[1][0][d] + comb[2][0][d] + comb[3][0][d];
    float aK = comb[0][1][d] + comb[1][1][d] + comb[2][1][d] + comb[3][1][d];
    float aS = comb[0][2][d] + comb[1][2][d] + comb[2][2][d] + comb[3][2][d];
    int tK = scn[0][0] + scn[1][0] + scn[2][0] + scn[3][0];
    int tS = scn[0][1] + scn[1][1] + scn[2][1] + scn[3][1];
    float invK = 1.f / ((float)tK + 1e-30f);
    float invS = 1.f / ((float)tS + 1e-30f);

    float* ag = g_agg + (size_t)bw * 384;
    ag[d]       = aO;               // H-space, bias included
    ag[128 + d] = aK * invK;
    ag[256 + d] = aS * invS;
    if (tid == 0) {
        g_coef[bw * 4 + 1] = (float)tK * invK;
        g_coef[bw * 4 + 2] = (float)tS * invS;
        int pos = atomicAdd(&g_n, 1);
        g_list[pos] = bw;
        atomicAdd(&g_bcnt[b], 1);
    }
}

// ---------------- k_update word-group processor (R3-proven math, templated G) ----------------
template<int G>
__device__ __forceinline__ void process_group(
    int base, int N, int tg, int half, int lane, int t64, int dim0,
    const float* __restrict__ wk_W, const float* __restrict__ wk_b,
    const float* __restrict__ ws_W, const float* __restrict__ ws_b,
    const float* __restrict__ up_W, const float* __restrict__ up_b,
    float (&as)[4][GMAIN_][128], float (&hs)[4][GMAIN_][128], float (&ssp)[4][GMAIN_][2])
{
    int idx[G]; bool val[G];
    #pragma unroll
    for (int g = 0; g < G; ++g) {
        val[g] = (base + g) < N;
        idx[g] = val[g] ? g_list[base + g] : 0;
    }
    const float2 bU = *(const float2*)(up_b + dim0);
    float2 u[G];
    #pragma unroll
    for (int g = 0; g < G; ++g) u[g] = bU;

    #pragma unroll
    for (int p = 0; p < 3; ++p) {
        // stage aggregates for this part
        for (int q = t64; q < G * 32; q += 64) {
            int g = q >> 5, off = (q & 31) * 4;
            float4 v = val[g] ? *(const float4*)(g_agg + (size_t)idx[g] * 384 + p * 128 + off)
                              : make_float4(0.f,0.f,0.f,0.f);
            *(float4*)(&as[tg][g][off]) = v;
        }
        team_bar(tg);

        float2 h[G];
        if (p == 0) {
            #pragma unroll
            for (int g = 0; g < G; ++g) h[g] = *(const float2*)(&as[tg][g][dim0]);
        } else {
            const float* Wp = (p == 1) ? wk_W : ws_W;
            const float* bp = (p == 1) ? wk_b : ws_b;
            const float2 bia = *(const float2*)(bp + dim0);
            #pragma unroll
            for (int g = 0; g < G; ++g) {
                float cf = val[g] ? g_coef[idx[g] * 4 + p] : 0.f;
                h[g] = make_float2(cf * bia.x, cf * bia.y);
            }
            #pragma unroll 4
            for (int s4 = 0; s4 < 32; ++s4) {
                float2 w0 = *(const float2*)(Wp + (s4 * 4 + 0) * 128 + dim0);
                float2 w1 = *(const float2*)(Wp + (s4 * 4 + 1) * 128 + dim0);
                float2 w2 = *(const float2*)(Wp + (s4 * 4 + 2) * 128 + dim0);
                float2 w3 = *(const float2*)(Wp + (s4 * 4 + 3) * 128 + dim0);
                #pragma unroll
                for (int g = 0; g < G; ++g) {
                    float4 av = *(const float4*)(&as[tg][g][s4 * 4]);
                    h[g].x = fmaf(av.x, w0.x, fmaf(av.y, w1.x, fmaf(av.z, w2.x, fmaf(av.w, w3.x, h[g].x))));
                    h[g].y = fmaf(av.x, w0.y, fmaf(av.y, w1.y, fmaf(av.z, w2.y, fmaf(av.w, w3.y, h[g].y))));
                }
            }
        }
        // L2 norm across team
        #pragma unroll
        for (int g = 0; g < G; ++g) {
            float ss = h[g].x * h[g].x + h[g].y * h[g].y;
            ss += __shfl_xor_sync(0xffffffffu, ss, 16);
            ss += __shfl_xor_sync(0xffffffffu, ss, 8);
            ss += __shfl_xor_sync(0xffffffffu, ss, 4);
            ss += __shfl_xor_sync(0xffffffffu, ss, 2);
            ss += __shfl_xor_sync(0xffffffffu, ss, 1);
            if (lane == 0) ssp[tg][g][half] = ss;
        }
        team_bar(tg);
        #pragma unroll
        for (int g = 0; g < G; ++g) {
            float inv = 1.f / (sqrtf(ssp[tg][g][0] + ssp[tg][g][1]) + 1e-30f);
            *(float2*)(&hs[tg][g][dim0]) = make_float2(h[g].x * inv, h[g].y * inv);
        }
        team_bar(tg);
        // up-projection for this part
        const float* Up = up_W + (size_t)p * 128 * 128;
        #pragma unroll 4
        for (int s4 = 0; s4 < 32; ++s4) {
            float2 w0 = *(const float2*)(Up + (s4 * 4 + 0) * 128 + dim0);
            float2 w1 = *(const float2*)(Up + (s4 * 4 + 1) * 128 + dim0);
            float2 w2 = *(const float2*)(Up + (s4 * 4 + 2) * 128 + dim0);
            float2 w3 = *(const float2*)(Up + (s4 * 4 + 3) * 128 + dim0);
            #pragma unroll
            for (int g = 0; g < G; ++g) {
                float4 hv = *(const float4*)(&hs[tg][g][s4 * 4]);
                u[g].x = fmaf(hv.x, w0.x, fmaf(hv.y, w1.x, fmaf(hv.z, w2.x, fmaf(hv.w, w3.x, u[g].x))));
                u[g].y = fmaf(hv.x, w0.y, fmaf(hv.y, w1.y, fmaf(hv.z, w2.y, fmaf(hv.w, w3.y, u[g].y))));
            }
        }
        team_bar(tg);  // protect as/hs reuse in next part
    }
    // relu + pooled accumulation
    #pragma unroll
    for (int g = 0; g < G; ++g) {
        if (val[g]) {
            int b = idx[g] >> 11;
            atomicAdd(g_goal + b * 128 + dim0,     fmaxf(u[g].x, 0.f));
            atomicAdd(g_goal + b * 128 + dim0 + 1, fmaxf(u[g].y, 0.f));
        }
    }
}

// ---------------- kernel 3: update + fused finale ----------------
// 148 blocks x 256 threads -> 592 two-warp teams, G=5 words each (perfect
// coverage of N~2950); 1-word stride cleanup for N>2960. After a resident-grid
// done-counter barrier, blocks 0..7 compute the gate finale (one batch each).
__global__ void __launch_bounds__(256) k_update(
    const float* __restrict__ wk_W, const float* __restrict__ wk_b,
    const float* __restrict__ ws_W, const float* __restrict__ ws_b,
    const float* __restrict__ up_W, const float* __restrict__ up_b,
    const float* __restrict__ node_hidden,
    const float* __restrict__ wg_W, const float* __restrict__ wg_b,
    const float* __restrict__ fg_W, const float* __restrict__ fg_b,
    float* __restrict__ out)
{
    const int tid = threadIdx.x;
    const int lane = tid & 31, wid = tid >> 5;
    const int half = wid & 1, tg = wid >> 1;
    const int t64 = tid & 63;
    const int team = blockIdx.x * 4 + tg;
    const int N = g_n;
    const int dim0 = half * 64 + lane * 2;

    __shared__ float as[4][GMAIN_][128];
    __shared__ float hs[4][GMAIN_][128];
    __shared__ float ssp[4][GMAIN_][2];

    // main pass: G=5, static perfect-balance assignment
    {
        int base = team * GMAIN_;
        if (base < N && base < NTEAMS_ * GMAIN_)
            process_group<GMAIN_>(base, N, tg, half, lane, t64, dim0,
                                  wk_W, wk_b, ws_W, ws_b, up_W, up_b, as, hs, ssp);
    }
    // cleanup pass: words beyond NTEAMS_*GMAIN_ (rare), one per team per round
    for (int w0 = NTEAMS_ * GMAIN_ + team; w0 < N; w0 += NTEAMS_)
        process_group<1>(w0, N, tg, half, lane, t64, dim0,
                         wk_W, wk_b, ws_W, ws_b, up_W, up_b, as, hs, ssp);

    // ---- resident-grid barrier ----
    __syncthreads();
    if (tid == 0) {
        __threadfence();
        atomicAdd(&g_done, 1);
    }
    if (blockIdx.x >= B_) return;

    if (tid == 0) {
        while (atomicAdd(&g_done, 0) < (int)gridDim.x) { }
    }
    __syncthreads();

    // ---- finale for batch b = blockIdx.x ----
    const int b = blockIdx.x;
    const int d = tid & 127, kh = tid >> 7;
    __shared__ float gws[128], nh[128], pp1[2][128], pp2[2][128];
    if (tid < 128) {
        float inv = 1.f / ((float)g_bcnt[b] + 1e-30f);
        gws[tid] = __ldcg(&g_goal[b * 128 + tid]) * inv;
        nh[tid] = node_hidden[b * 128 + tid];
    }
    __syncthreads();

    float s1 = 0.f, s2 = 0.f;
    #pragma unroll 4
    for (int i = 0; i < 64; ++i) {
        int k = kh * 64 + i;
        s1 = fmaf(gws[k], wg_W[k * 128 + d], s1);
    }
    #pragma unroll 4
    for (int i = 0; i < 128; ++i) {
        int k = kh * 128 + i;
        float x = (k < 128) ? gws[k] : nh[k - 128];
        s2 = fmaf(x, fg_W[k * 128 + d], s2);
    }
    pp1[kh][d] = s1; pp2[kh][d] = s2;
    __syncthreads();

    if (tid < 128) {
        float t1 = pp1[0][tid] + pp1[1][tid] + wg_b[tid];
        float t2 = pp2[0][tid] + pp2[1][tid] + fg_b[tid];
        float gu = fmaxf(t1, 0.f);
        float f  = 1.f / (1.f + expf(-t2));
        out[b * 128 + tid] = fmaxf(f, 0.1f) * nh[tid] + (1.f - f) * gu;
    }
}

// ---------------- launch ----------------
extern "C" void kernel_launch(void* const* d_in, const int* in_sizes, int n_in,
                              void* d_out, int out_size) {
    const float* word_outputs      = (const float*)d_in[0];
    const float* node_hidden       = (const float*)d_in[1];
    const float* op_embedding      = (const float*)d_in[2];
    const float* word_operator     = (const float*)d_in[3];
    const float* word_word         = (const float*)d_in[4];
    const float* depend_relation   = (const float*)d_in[5];
    const float* word_exist_matrix = (const float*)d_in[6];
    const float* word_exist_seq    = (const float*)d_in[7];
    const float* goal_word         = (const float*)d_in[8];
    const float* o_w_W = (const float*)d_in[9];
    const float* o_w_b = (const float*)d_in[10];
    const float* wk_W  = (const float*)d_in[11];
    const float* wk_b  = (const float*)d_in[12];
    const float* ws_W  = (const float*)d_in[13];
    const float* ws_b  = (const float*)d_in[14];
    const float* up_W  = (const float*)d_in[15];
    const float* up_b  = (const float*)d_in[16];
    const float* wg_W  = (const float*)d_in[17];
    const float* wg_b  = (const float*)d_in[18];
    const float* fg_W  = (const float*)d_in[19];
    const float* fg_b  = (const float*)d_in[20];
    float* out = (float*)d_out;

    k_opproj<<<dim3(8, 8), 1024>>>(op_embedding, o_w_W, o_w_b);
    k_aggregate<<<dim3(W_, B_), 128>>>(word_outputs, word_operator, word_word,
                                       depend_relation, word_exist_matrix,
                                       word_exist_seq, goal_word);
    k_update<<<NBLK_, 256>>>(wk_W, wk_b, ws_W, ws_b, up_W, up_b,
                             node_hidden, wg_W, wg_b, fg_W, fg_b, out);
}

// round 13
// speedup vs baseline: 1.2760x; 1.2391x over previous
#include <cuda_runtime.h>

#define S_   4
#define B_   8
#define L_   512
#define D_   128
#define NOP_ 64
#define W_   2048   // S_*L_

// ---------------- scratch (device globals; no allocation) ----------------
__device__ float g_agg[B_ * W_ * 3 * D_];   // per selected word: [a_o | a_k(normed) | a_s(normed)]
__device__ float g_coef[B_ * W_ * 4];       // [cO, rowsumK, rowsumS]
__device__ float g_goal[B_ * D_];           // pooled sum of relu(word_updated)
__device__ int   g_bcnt[B_];
__device__ int   g_list[B_ * W_];
__device__ int   g_n;

// ---------------- helpers ----------------
__device__ __forceinline__ void add4(float4& a, const float4 v) {
    a.x += v.x; a.y += v.y; a.z += v.z; a.w += v.w;
}
__device__ __forceinline__ void team_bar(int tg) {
    asm volatile("bar.sync %0, 64;" :: "r"(tg + 1) : "memory");
}

// ---------------- kernel 0: reset ----------------
__global__ void k_reset() {
    int t = threadIdx.x;
    if (t < B_ * D_) g_goal[t] = 0.f;
    if (t < B_) g_bcnt[t] = 0;
    if (t == 0) g_n = 0;
}

// ---------------- kernel 1: aggregate neighbors (R3-proven form) ----------------
// grid (W_, B_), block 128; early exit for non-goal words. Float4 mask reads,
// index lists staged in smem, gathers with MLP-4 accumulators. Operator part
// gathers RAW op_embedding rows (D-space); projection happens in k_update.
__global__ void __launch_bounds__(128) k_aggregate(
    const float* __restrict__ word_outputs,
    const float* __restrict__ op_embedding,
    const float* __restrict__ word_operator,
    const float* __restrict__ word_word,
    const float* __restrict__ depend_relation,
    const float* __restrict__ word_exist_matrix,
    const float* __restrict__ word_exist_seq,
    const float* __restrict__ goal_word)
{
    const int w = blockIdx.x, b = blockIdx.y;
    const int bw = b * W_ + w;
    if (goal_word[bw] == 0.f || word_exist_seq[bw] == 0.f) return;

    const int tid = threadIdx.x;
    const int lane = tid & 31, wid = tid >> 5;
    const unsigned lt = (1u << lane) - 1u;

    __shared__ int   listK[4][512];
    __shared__ int   listS[4][128];
    __shared__ int   listO[64];
    __shared__ float comb[4][3][128];
    __shared__ int   scn[4][2];

    float4 accO = {0,0,0,0}, accK = {0,0,0,0}, accS = {0,0,0,0};
    int cK = 0, cS = 0, cOv = 0;

    // ---- operator part: gather raw op_embedding rows, warp 0 only ----
    if (wid == 0) {
        const float4* wo4 = (const float4*)(word_operator + (size_t)bw * NOP_);
        float4 m = (lane < 16) ? wo4[lane] : make_float4(0.f,0.f,0.f,0.f);
        int col0 = lane * 4, cO = 0;
        unsigned bb;
        bb = __ballot_sync(0xffffffffu, m.x != 0.f); if (m.x != 0.f) listO[cO + __popc(bb & lt)] = col0;     cO += __popc(bb);
        bb = __ballot_sync(0xffffffffu, m.y != 0.f); if (m.y != 0.f) listO[cO + __popc(bb & lt)] = col0 + 1; cO += __popc(bb);
        bb = __ballot_sync(0xffffffffu, m.z != 0.f); if (m.z != 0.f) listO[cO + __popc(bb & lt)] = col0 + 2; cO += __popc(bb);
        bb = __ballot_sync(0xffffffffu, m.w != 0.f); if (m.w != 0.f) listO[cO + __popc(bb & lt)] = col0 + 3; cO += __popc(bb);
        __syncwarp();
        const float* pb = op_embedding + (size_t)b * NOP_ * D_;
        float4 o0 = {0,0,0,0}, o1 = {0,0,0,0};
        int i = 0;
        for (; i + 2 <= cO; i += 2) {
            float4 v0 = ((const float4*)(pb + (size_t)listO[i]     * D_))[lane];
            float4 v1 = ((const float4*)(pb + (size_t)listO[i + 1] * D_))[lane];
            add4(o0, v0); add4(o1, v1);
        }
        if (i < cO) add4(o0, ((const float4*)(pb + (size_t)listO[i] * D_))[lane]);
        accO = o0; add4(accO, o1);
        cOv = cO;
    }

    // ---- knowledge part: word_word * word_exist_matrix over 2048 cols ----
    {
        const float4* ww4 = (const float4*)(word_word + (size_t)bw * W_);
        const float4* we4 = (const float4*)(word_exist_matrix + (size_t)bw * W_);
        const int cbase = wid * 512;
        #pragma unroll
        for (int c4 = 0; c4 < 4; ++c4) {
            int vec = wid * 128 + c4 * 32 + lane;
            float4 m1 = ww4[vec], m2 = we4[vec];
            float mx = m1.x * m2.x, my = m1.y * m2.y, mz = m1.z * m2.z, mw = m1.w * m2.w;
            int col0 = cbase + c4 * 128 + lane * 4;
            unsigned bb;
            bb = __ballot_sync(0xffffffffu, mx != 0.f); if (mx != 0.f) listK[wid][cK + __popc(bb & lt)] = col0;     cK += __popc(bb);
            bb = __ballot_sync(0xffffffffu, my != 0.f); if (my != 0.f) listK[wid][cK + __popc(bb & lt)] = col0 + 1; cK += __popc(bb);
            bb = __ballot_sync(0xffffffffu, mz != 0.f); if (mz != 0.f) listK[wid][cK + __popc(bb & lt)] = col0 + 2; cK += __popc(bb);
            bb = __ballot_sync(0xffffffffu, mw != 0.f); if (mw != 0.f) listK[wid][cK + __popc(bb & lt)] = col0 + 3; cK += __popc(bb);
        }
        __syncwarp();
        float4 k0 = {0,0,0,0}, k1 = {0,0,0,0}, k2 = {0,0,0,0}, k3 = {0,0,0,0};
        int i = 0;
        for (; i + 4 <= cK; i += 4) {
            int j0 = listK[wid][i], j1 = listK[wid][i+1], j2 = listK[wid][i+2], j3 = listK[wid][i+3];
            float4 v0 = ((const float4*)(word_outputs + (((size_t)(j0 >> 9) * B_ + b) * L_ + (j0 & 511)) * D_))[lane];
            float4 v1 = ((const float4*)(word_outputs + (((size_t)(j1 >> 9) * B_ + b) * L_ + (j1 & 511)) * D_))[lane];
            float4 v2 = ((const float4*)(word_outputs + (((size_t)(j2 >> 9) * B_ + b) * L_ + (j2 & 511)) * D_))[lane];
            float4 v3 = ((const float4*)(word_outputs + (((size_t)(j3 >> 9) * B_ + b) * L_ + (j3 & 511)) * D_))[lane];
            add4(k0, v0); add4(k1, v1); add4(k2, v2); add4(k3, v3);
        }
        for (; i < cK; ++i) {
            int j0 = listK[wid][i];
            add4(k0, ((const float4*)(word_outputs + (((size_t)(j0 >> 9) * B_ + b) * L_ + (j0 & 511)) * D_))[lane]);
        }
        add4(k0, k1); add4(k2, k3); accK = k0; add4(accK, k2);
    }

    // ---- segment dependency part: 512 cols, same segment ----
    {
        const int s = w >> 9, l = w & 511;
        const float4* dp4 = (const float4*)(depend_relation + (((size_t)s * B_ + b) * L_ + l) * L_);
        const float* xb = word_outputs + ((size_t)s * B_ + b) * L_ * D_;
        float4 m = dp4[wid * 32 + lane];
        int col0 = wid * 128 + lane * 4;
        unsigned bb;
        bb = __ballot_sync(0xffffffffu, m.x != 0.f); if (m.x != 0.f) listS[wid][cS + __popc(bb & lt)] = col0;     cS += __popc(bb);
        bb = __ballot_sync(0xffffffffu, m.y != 0.f); if (m.y != 0.f) listS[wid][cS + __popc(bb & lt)] = col0 + 1; cS += __popc(bb);
        bb = __ballot_sync(0xffffffffu, m.z != 0.f); if (m.z != 0.f) listS[wid][cS + __popc(bb & lt)] = col0 + 2; cS += __popc(bb);
        bb = __ballot_sync(0xffffffffu, m.w != 0.f); if (m.w != 0.f) listS[wid][cS + __popc(bb & lt)] = col0 + 3; cS += __popc(bb);
        __syncwarp();
        float4 s0 = {0,0,0,0}, s1 = {0,0,0,0}, s2 = {0,0,0,0}, s3 = {0,0,0,0};
        int i = 0;
        for (; i + 4 <= cS; i += 4) {
            int j0 = listS[wid][i], j1 = listS[wid][i+1], j2 = listS[wid][i+2], j3 = listS[wid][i+3];
            float4 v0 = ((const float4*)(xb + (size_t)j0 * D_))[lane];
            float4 v1 = ((const float4*)(xb + (size_t)j1 * D_))[lane];
            float4 v2 = ((const float4*)(xb + (size_t)j2 * D_))[lane];
            float4 v3 = ((const float4*)(xb + (size_t)j3 * D_))[lane];
            add4(s0, v0); add4(s1, v1); add4(s2, v2); add4(s3, v3);
        }
        for (; i < cS; ++i)
            add4(s0, ((const float4*)(xb + (size_t)listS[wid][i] * D_))[lane]);
        add4(s0, s1); add4(s2, s3); accS = s0; add4(accS, s2);
    }

    // ---- cross-warp combine ----
    *(float4*)&comb[wid][0][4 * lane] = accO;
    *(float4*)&comb[wid][1][4 * lane] = accK;
    *(float4*)&comb[wid][2][4 * lane] = accS;
    if (lane == 0) { scn[wid][0] = cK; scn[wid][1] = cS; }
    __syncthreads();

    const int d = tid;
    float aO = comb[0][0][d] + comb[1][0][d] + comb[2][0][d] + comb[3][0][d];
    float aK = comb[0][1][d] + comb[1][1][d] + comb[2][1][d] + comb[3][1][d];
    float aS = comb[0][2][d] + comb[1][2][d] + comb[2][2][d] + comb[3][2][d];
    int tK = scn[0][0] + scn[1][0] + scn[2][0] + scn[3][0];
    int tS = scn[0][1] + scn[1][1] + scn[2][1] + scn[3][1];
    float invK = 1.f / ((float)tK + 1e-30f);
    float invS = 1.f / ((float)tS + 1e-30f);

    float* ag = g_agg + (size_t)bw * 384;
    ag[d]       = aO;               // raw op-embedding sum (D-space)
    ag[128 + d] = aK * invK;
    ag[256 + d] = aS * invS;
    if (tid == 0) {
        g_coef[bw * 4 + 0] = (float)cOv;            // operator bias scale (no norm)
        g_coef[bw * 4 + 1] = (float)tK * invK;      // row-sum of normalized adj
        g_coef[bw * 4 + 2] = (float)tS * invS;
        int pos = atomicAdd(&g_n, 1);
        g_list[pos] = bw;
        atomicAdd(&g_bcnt[b], 1);
    }
}

// ---------------- kernel 2: 3 GEMVs + norms + up-proj + pooled REDG ----------------
// 2-warp teams; each team does 8 words, each warp 64 of 128 output dims.
// a and normalized h staged in smem (LDS.128 broadcast).
__global__ void __launch_bounds__(256) k_update(
    const float* __restrict__ o_w_W, const float* __restrict__ o_w_b,
    const float* __restrict__ wk_W,  const float* __restrict__ wk_b,
    const float* __restrict__ ws_W,  const float* __restrict__ ws_b,
    const float* __restrict__ up_W,  const float* __restrict__ up_b)
{
    const int tid = threadIdx.x;
    const int lane = tid & 31, wid = tid >> 5;
    const int half = wid & 1, tg = wid >> 1;
    const int t64 = tid & 63;
    const int team = blockIdx.x * 4 + tg;
    const int nteams = gridDim.x * 4;
    const int N = g_n;
    const int dim0 = half * 64 + lane * 2;

    __shared__ float as[4][8][128];
    __shared__ float hs[4][8][128];
    __shared__ float ssp[4][8][2];

    const float2 bU = *(const float2*)(up_b + dim0);
    const float* Wf[3] = { o_w_W, wk_W, ws_W };
    const float* bf[3] = { o_w_b, wk_b, ws_b };

    for (int base = team * 8; base < N; base += nteams * 8) {
        int idx[8]; bool val[8];
        #pragma unroll
        for (int g = 0; g < 8; ++g) {
            val[g] = (base + g) < N;
            idx[g] = val[g] ? g_list[base + g] : 0;
        }
        float2 u[8];
        #pragma unroll
        for (int g = 0; g < 8; ++g) u[g] = bU;

        #pragma unroll
        for (int p = 0; p < 3; ++p) {
            // stage aggregates for this part
            #pragma unroll
            for (int r = 0; r < 4; ++r) {
                int q = r * 64 + t64;
                int g = q >> 5, off = (q & 31) * 4;
                float4 v = val[g] ? *(const float4*)(g_agg + (size_t)idx[g] * 384 + p * 128 + off)
                                  : make_float4(0.f,0.f,0.f,0.f);
                *(float4*)(&as[tg][g][off]) = v;
            }
            team_bar(tg);

            const float* Wp = Wf[p];
            const float2 bia = *(const float2*)(bf[p] + dim0);
            float2 h[8];
            #pragma unroll
            for (int g = 0; g < 8; ++g) {
                float cf = val[g] ? g_coef[idx[g] * 4 + p] : 0.f;
                h[g] = make_float2(cf * bia.x, cf * bia.y);
            }
            #pragma unroll 4
            for (int s4 = 0; s4 < 32; ++s4) {
                float2 w0 = *(const float2*)(Wp + (s4 * 4 + 0) * 128 + dim0);
                float2 w1 = *(const float2*)(Wp + (s4 * 4 + 1) * 128 + dim0);
                float2 w2 = *(const float2*)(Wp + (s4 * 4 + 2) * 128 + dim0);
                float2 w3 = *(const float2*)(Wp + (s4 * 4 + 3) * 128 + dim0);
                #pragma unroll
                for (int g = 0; g < 8; ++g) {
                    float4 av = *(const float4*)(&as[tg][g][s4 * 4]);
                    h[g].x = fmaf(av.x, w0.x, fmaf(av.y, w1.x, fmaf(av.z, w2.x, fmaf(av.w, w3.x, h[g].x))));
                    h[g].y = fmaf(av.x, w0.y, fmaf(av.y, w1.y, fmaf(av.z, w2.y, fmaf(av.w, w3.y, h[g].y))));
                }
            }
            // L2 norm across the team (warp half-reduction + smem exchange)
            #pragma unroll
            for (int g = 0; g < 8; ++g) {
                float ss = h[g].x * h[g].x + h[g].y * h[g].y;
                ss += __shfl_xor_sync(0xffffffffu, ss, 16);
                ss += __shfl_xor_sync(0xffffffffu, ss, 8);
                ss += __shfl_xor_sync(0xffffffffu, ss, 4);
                ss += __shfl_xor_sync(0xffffffffu, ss, 2);
                ss += __shfl_xor_sync(0xffffffffu, ss, 1);
                if (lane == 0) ssp[tg][g][half] = ss;
            }
            team_bar(tg);
            #pragma unroll
            for (int g = 0; g < 8; ++g) {
                float inv = 1.f / (sqrtf(ssp[tg][g][0] + ssp[tg][g][1]) + 1e-30f);
                *(float2*)(&hs[tg][g][dim0]) = make_float2(h[g].x * inv, h[g].y * inv);
            }
            team_bar(tg);
            // up-projection accumulate for this part
            const float* Up = up_W + (size_t)p * 128 * 128;
            #pragma unroll 4
            for (int s4 = 0; s4 < 32; ++s4) {
                float2 w0 = *(const float2*)(Up + (s4 * 4 + 0) * 128 + dim0);
                float2 w1 = *(const float2*)(Up + (s4 * 4 + 1) * 128 + dim0);
                float2 w2 = *(const float2*)(Up + (s4 * 4 + 2) * 128 + dim0);
                float2 w3 = *(const float2*)(Up + (s4 * 4 + 3) * 128 + dim0);
                #pragma unroll
                for (int g = 0; g < 8; ++g) {
                    float4 hv = *(const float4*)(&hs[tg][g][s4 * 4]);
                    u[g].x = fmaf(hv.x, w0.x, fmaf(hv.y, w1.x, fmaf(hv.z, w2.x, fmaf(hv.w, w3.x, u[g].x))));
                    u[g].y = fmaf(hv.x, w0.y, fmaf(hv.y, w1.y, fmaf(hv.z, w2.y, fmaf(hv.w, w3.y, u[g].y))));
                }
            }
            team_bar(tg);  // protect as/hs reuse in next part
        }
        // relu + pooled accumulation
        #pragma unroll
        for (int g = 0; g < 8; ++g) {
            if (val[g]) {
                int b = idx[g] >> 11;
                atomicAdd(g_goal + b * 128 + dim0,     fmaxf(u[g].x, 0.f));
                atomicAdd(g_goal + b * 128 + dim0 + 1, fmaxf(u[g].y, 0.f));
            }
        }
    }
}

// ---------------- kernel 3: gates + output (R3-proven form) ----------------
__global__ void __launch_bounds__(1024) k_final(
    const float* __restrict__ node_hidden,
    const float* __restrict__ wg_W, const float* __restrict__ wg_b,
    const float* __restrict__ fg_W, const float* __restrict__ fg_b,
    float* __restrict__ out)
{
    const int b = blockIdx.x;
    const int tid = threadIdx.x;
    const int d = tid & 127, kq = tid >> 7;
    __shared__ float gws[128], nh[128];
    __shared__ float p1[8][128], p2[8][128];

    if (tid < 128) {
        float inv = 1.f / ((float)g_bcnt[b] + 1e-30f);
        gws[tid] = g_goal[b * 128 + tid] * inv;
        nh[tid] = node_hidden[b * 128 + tid];
    }
    __syncthreads();

    float s1 = 0.f, s2 = 0.f;
    #pragma unroll
    for (int kk = 0; kk < 16; ++kk) {
        int k = kq * 16 + kk;
        s1 = fmaf(gws[k], wg_W[k * 128 + d], s1);
    }
    #pragma unroll
    for (int kk = 0; kk < 32; ++kk) {
        int k = kq * 32 + kk;
        float x = (k < 128) ? gws[k] : nh[k - 128];
        s2 = fmaf(x, fg_W[k * 128 + d], s2);
    }
    p1[kq][d] = s1; p2[kq][d] = s2;
    __syncthreads();

    if (tid < 128) {
        float t1 = wg_b[tid], t2 = fg_b[tid];
        #pragma unroll
        for (int q = 0; q < 8; ++q) { t1 += p1[q][tid]; t2 += p2[q][tid]; }
        float gu = fmaxf(t1, 0.f);
        float f = 1.f / (1.f + expf(-t2));
        out[b * 128 + tid] = fmaxf(f, 0.1f) * nh[tid] + (1.f - f) * gu;
    }
}

// ---------------- launch ----------------
extern "C" void kernel_launch(void* const* d_in, const int* in_sizes, int n_in,
                              void* d_out, int out_size) {
    const float* word_outputs      = (const float*)d_in[0];
    const float* node_hidden       = (const float*)d_in[1];
    const float* op_embedding      = (const float*)d_in[2];
    const float* word_operator     = (const float*)d_in[3];
    const float* word_word         = (const float*)d_in[4];
    const float* depend_relation   = (const float*)d_in[5];
    const float* word_exist_matrix = (const float*)d_in[6];
    const float* word_exist_seq    = (const float*)d_in[7];
    const float* goal_word         = (const float*)d_in[8];
    const float* o_w_W = (const float*)d_in[9];
    const float* o_w_b = (const float*)d_in[10];
    const float* wk_W  = (const float*)d_in[11];
    const float* wk_b  = (const float*)d_in[12];
    const float* ws_W  = (const float*)d_in[13];
    const float* ws_b  = (const float*)d_in[14];
    const float* up_W  = (const float*)d_in[15];
    const float* up_b  = (const float*)d_in[16];
    const float* wg_W  = (const float*)d_in[17];
    const float* wg_b  = (const float*)d_in[18];
    const float* fg_W  = (const float*)d_in[19];
    const float* fg_b  = (const float*)d_in[20];
    float* out = (float*)d_out;

    k_reset<<<1, 1024>>>();
    k_aggregate<<<dim3(W_, B_), 128>>>(word_outputs, op_embedding, word_operator,
                                       word_word, depend_relation, word_exist_matrix,
                                       word_exist_seq, goal_word);
    k_update<<<148, 256>>>(o_w_W, o_w_b, wk_W, wk_b, ws_W, ws_b, up_W, up_b);
    k_final<<<B_, 1024>>>(node_hidden, wg_W, wg_b, fg_W, fg_b, out);
}